// round 10
// baseline (speedup 1.0000x reference)
#include <cuda_runtime.h>
#include <cuda_fp16.h>
#include <cstdint>
#include <math.h>

#define NNODES 100000
#define NEDGES 3200000
#define NFEAT  256
#define NHID   128
#define NCLASS 40

#define SCAN_B  1024
#define SCAN_NB ((NNODES + SCAN_B - 1) / SCAN_B)   // 98

// ---------------- scratch ----------------
__device__ float  g_Self[(size_t)NNODES * NHID];
__device__ __half g_Ph[(size_t)NNODES * NHID];     // neighbor projection, fp16
__device__ float  g_H[(size_t)NNODES * NHID];
__device__ int    g_deg[NNODES];
__device__ int    g_rowptr[NNODES + 1];
__device__ int    g_cursor[NNODES];
__device__ int    g_colidx[NEDGES];
__device__ float  g_invdeg[NNODES];
__device__ int    g_blocksum[SCAN_NB];

// ---------------- CSR build ----------------
__global__ void k_zero_deg() {
    int i = blockIdx.x * blockDim.x + threadIdx.x;
    if (i < NNODES) g_deg[i] = 0;
}
__global__ void k_hist(const int* __restrict__ rows, int E) {
    int e = blockIdx.x * blockDim.x + threadIdx.x;
    if (e < E) atomicAdd(&g_deg[rows[e]], 1);
}

__global__ void k_scan1() {
    __shared__ int wsum[32];
    int tid = threadIdx.x, lane = tid & 31, wid = tid >> 5;
    int i = blockIdx.x * SCAN_B + tid;
    int v = (i < NNODES) ? g_deg[i] : 0;
    #pragma unroll
    for (int o = 16; o > 0; o >>= 1)
        v += __shfl_xor_sync(0xffffffffu, v, o);
    if (lane == 0) wsum[wid] = v;
    __syncthreads();
    if (wid == 0) {
        int y = wsum[lane];
        #pragma unroll
        for (int o = 16; o > 0; o >>= 1)
            y += __shfl_xor_sync(0xffffffffu, y, o);
        if (lane == 0) g_blocksum[blockIdx.x] = y;
    }
}

__global__ void k_scan2() {
    __shared__ int s[128];
    int tid = threadIdx.x;
    int v = (tid < SCAN_NB) ? g_blocksum[tid] : 0;
    s[tid] = v;
    __syncthreads();
    #pragma unroll
    for (int o = 1; o < 128; o <<= 1) {
        int t = (tid >= o) ? s[tid - o] : 0;
        __syncthreads();
        s[tid] += t;
        __syncthreads();
    }
    if (tid < SCAN_NB) g_blocksum[tid] = s[tid] - v;   // exclusive
    if (tid == 127) g_rowptr[NNODES] = s[127];
}

__global__ void k_scan3() {
    __shared__ int wsum[32];
    int tid = threadIdx.x, lane = tid & 31, wid = tid >> 5;
    int i = blockIdx.x * SCAN_B + tid;
    int v = (i < NNODES) ? g_deg[i] : 0;
    int x = v;
    #pragma unroll
    for (int o = 1; o < 32; o <<= 1) {
        int t = __shfl_up_sync(0xffffffffu, x, o);
        if (lane >= o) x += t;
    }
    if (lane == 31) wsum[wid] = x;
    __syncthreads();
    if (wid == 0) {
        int y = wsum[lane];
        #pragma unroll
        for (int o = 1; o < 32; o <<= 1) {
            int t = __shfl_up_sync(0xffffffffu, y, o);
            if (lane >= o) y += t;
        }
        wsum[lane] = y;
    }
    __syncthreads();
    if (i < NNODES) {
        int incl = x + (wid > 0 ? wsum[wid - 1] : 0) + g_blocksum[blockIdx.x];
        int excl = incl - v;
        g_rowptr[i] = excl;
        g_cursor[i] = excl;
        g_invdeg[i] = 1.0f / ((float)v + 1.0f);
    }
}

__global__ void k_scatter(const int* __restrict__ rows, const int* __restrict__ cols, int E) {
    int e = blockIdx.x * blockDim.x + threadIdx.x;
    if (e < E) {
        int r = rows[e];
        int p = atomicAdd(&g_cursor[r], 1);
        g_colidx[p] = cols[e];
    }
}

// ============ tf32 mma.sync GEMM, merged slabs: tile 128 x 256 ==============
// B matrix rows 0..127 = W[m][0..K-1] (self), 128..255 = W[m-128][K..2K-1].
// Output cols 0..127 -> C0 fp32 (Self), 128..255 -> C1h fp16 (Ph).
// Block: 512 thr / 16 warps; warp tile 32(m) x 64(n); K chunks of 32, 2 stages.
#define ABUF_F 4608                    // 128*36 floats per A stage
#define BBUF_F 9216                    // 256*36 floats per B stage
#define BOFF   (2 * ABUF_F)
#define GEMM_SMEM_BYTES ((2 * ABUF_F + 2 * BBUF_F) * 4)   // 110,592 B

__global__ __launch_bounds__(512, 1) void mma_gemm_kernel(
    const float* __restrict__ A, const float* __restrict__ W,
    int K, int ldb,
    float* __restrict__ C0, __half* __restrict__ C1h, int Nrows)
{
    extern __shared__ float smemf[];
    const int tid = threadIdx.x;
    const int lane = tid & 31, wid = tid >> 5;
    const int warp_m = wid & 3;          // 0..3 -> 32-row slice
    const int warp_n = wid >> 2;         // 0..3 -> 64-col slice
    const int gid = lane >> 2, tig = lane & 3;
    const int tile0 = blockIdx.x * 128;
    const uint32_t smem_u32 = (uint32_t)__cvta_generic_to_shared(smemf);

    float acc[2][8][4];
    #pragma unroll
    for (int mi = 0; mi < 2; mi++)
        #pragma unroll
        for (int ni = 0; ni < 8; ni++)
            #pragma unroll
            for (int q = 0; q < 4; q++) acc[mi][ni][q] = 0.f;

    auto stage = [&](int s, int kc) {
        // A: 128 x 32 floats = 1024 float4, 512 threads -> 2 iters
        #pragma unroll
        for (int it = 0; it < 2; it++) {
            int idx = tid + (it << 9);
            int row = idx >> 3, kq = (idx & 7) << 2;
            int gr = tile0 + row;
            if (gr >= Nrows) gr = Nrows - 1;
            const float* ga = A + (size_t)gr * K + kc + kq;
            uint32_t da = smem_u32 + (uint32_t)((s * ABUF_F + row * 36 + kq) << 2);
            asm volatile("cp.async.ca.shared.global [%0], [%1], 16;" :: "r"(da), "l"(ga));
        }
        // B: 256 x 32 floats = 2048 float4 -> 4 iters
        #pragma unroll
        for (int it = 0; it < 4; it++) {
            int idx = tid + (it << 9);
            int row = idx >> 3, kq = (idx & 7) << 2;
            const float* gb = (row < 128)
                ? W + (size_t)row * ldb + kc + kq
                : W + (size_t)(row - 128) * ldb + K + kc + kq;
            uint32_t db = smem_u32 + (uint32_t)((BOFF + s * BBUF_F + row * 36 + kq) << 2);
            asm volatile("cp.async.ca.shared.global [%0], [%1], 16;" :: "r"(db), "l"(gb));
        }
        asm volatile("cp.async.commit_group;");
    };

    const int nch = K >> 5;
    stage(0, 0);

    for (int ch = 0; ch < nch; ch++) {
        const int s = ch & 1;
        if (ch + 1 < nch) {
            stage(s ^ 1, (ch + 1) << 5);
            asm volatile("cp.async.wait_group 1;");
        } else {
            asm volatile("cp.async.wait_group 0;");
        }
        __syncthreads();

        const float* Abuf = smemf + s * ABUF_F;
        const float* Bbuf = smemf + BOFF + s * BBUF_F;

        #pragma unroll
        for (int kb = 0; kb < 32; kb += 8) {
            uint32_t a[2][4];
            #pragma unroll
            for (int mi = 0; mi < 2; mi++) {
                int R = warp_m * 32 + mi * 16;
                a[mi][0] = __float_as_uint(Abuf[(R + gid) * 36 + kb + tig]);
                a[mi][1] = __float_as_uint(Abuf[(R + gid + 8) * 36 + kb + tig]);
                a[mi][2] = __float_as_uint(Abuf[(R + gid) * 36 + kb + tig + 4]);
                a[mi][3] = __float_as_uint(Abuf[(R + gid + 8) * 36 + kb + tig + 4]);
            }
            #pragma unroll
            for (int ni = 0; ni < 8; ni++) {
                int n0 = warp_n * 64 + ni * 8;
                uint32_t b0 = __float_as_uint(Bbuf[(n0 + gid) * 36 + kb + tig]);
                uint32_t b1 = __float_as_uint(Bbuf[(n0 + gid) * 36 + kb + tig + 4]);
                #pragma unroll
                for (int mi = 0; mi < 2; mi++) {
                    asm volatile(
                        "mma.sync.aligned.m16n8k8.row.col.f32.tf32.tf32.f32 "
                        "{%0,%1,%2,%3}, {%4,%5,%6,%7}, {%8,%9}, {%0,%1,%2,%3};"
                        : "+f"(acc[mi][ni][0]), "+f"(acc[mi][ni][1]),
                          "+f"(acc[mi][ni][2]), "+f"(acc[mi][ni][3])
                        : "r"(a[mi][0]), "r"(a[mi][1]), "r"(a[mi][2]), "r"(a[mi][3]),
                          "r"(b0), "r"(b1));
                }
            }
        }
        __syncthreads();
    }

    const bool half_out = (warp_n >= 2);          // cols 128..255 -> Ph
    #pragma unroll
    for (int mi = 0; mi < 2; mi++) {
        int r0 = tile0 + warp_m * 32 + mi * 16 + gid;
        #pragma unroll
        for (int ni = 0; ni < 8; ni++) {
            int cglob = warp_n * 64 + ni * 8 + tig * 2;
            if (half_out) {
                int c = cglob - 128;
                if (r0 < Nrows)
                    *reinterpret_cast<__half2*>(C1h + (size_t)r0 * 128 + c) =
                        __floats2half2_rn(acc[mi][ni][0], acc[mi][ni][1]);
                if (r0 + 8 < Nrows)
                    *reinterpret_cast<__half2*>(C1h + (size_t)(r0 + 8) * 128 + c) =
                        __floats2half2_rn(acc[mi][ni][2], acc[mi][ni][3]);
            } else {
                if (r0 < Nrows)
                    *reinterpret_cast<float2*>(C0 + (size_t)r0 * 128 + cglob) =
                        make_float2(acc[mi][ni][0], acc[mi][ni][1]);
                if (r0 + 8 < Nrows)
                    *reinterpret_cast<float2*>(C0 + (size_t)(r0 + 8) * 128 + cglob) =
                        make_float2(acc[mi][ni][2], acc[mi][ni][3]);
            }
        }
    }
}

// ========== Classifier: tf32 mma GEMM + fused bias + log_softmax ============
// Tile 128 rows x 64 cols (W zero-padded 40->64). 4 warps; each warp owns ALL
// 64 cols of its 32 rows -> row softmax reduces within a quad (shfl xor 1,2).
#define CLS_ABUF 4608                               // 128*36 per stage
#define CLS_BOFF (2 * CLS_ABUF)
#define CLS_BF   (64 * 132)
#define CLS_SMEM_BYTES ((2 * CLS_ABUF + CLS_BF) * 4)   // 70,656 B

__global__ __launch_bounds__(128, 2) void cls_mma_kernel(
    const float* __restrict__ A, const float* __restrict__ W,
    const float* __restrict__ bias, float* __restrict__ out, int Nrows)
{
    extern __shared__ float smemf[];
    float* Bs = smemf + CLS_BOFF;                  // [64][132]
    const int tid = threadIdx.x;
    const int lane = tid & 31, wid = tid >> 5;     // wid = warp_m
    const int gid = lane >> 2, tig = lane & 3;
    const int tile0 = blockIdx.x * 128;
    const uint32_t smem_u32 = (uint32_t)__cvta_generic_to_shared(smemf);

    // Load W (40x128) into padded Bs (64x128, rows 40..63 = 0)
    for (int idx = tid; idx < 64 * 128; idx += 128) {
        int r = idx >> 7, k = idx & 127;
        Bs[r * 132 + k] = (r < NCLASS) ? W[r * 128 + k] : 0.f;
    }

    float acc[2][8][4];
    #pragma unroll
    for (int mi = 0; mi < 2; mi++)
        #pragma unroll
        for (int ni = 0; ni < 8; ni++)
            #pragma unroll
            for (int q = 0; q < 4; q++) acc[mi][ni][q] = 0.f;

    auto stage = [&](int s, int kc) {
        #pragma unroll
        for (int it = 0; it < 8; it++) {
            int idx = tid + (it << 7);
            int row = idx >> 3, kq = (idx & 7) << 2;
            int gr = tile0 + row;
            if (gr >= Nrows) gr = Nrows - 1;
            const float* ga = A + (size_t)gr * NHID + kc + kq;
            uint32_t da = smem_u32 + (uint32_t)((s * CLS_ABUF + row * 36 + kq) << 2);
            asm volatile("cp.async.ca.shared.global [%0], [%1], 16;" :: "r"(da), "l"(ga));
        }
        asm volatile("cp.async.commit_group;");
    };

    stage(0, 0);

    #pragma unroll
    for (int ch = 0; ch < 4; ch++) {               // K = 128
        const int s = ch & 1;
        if (ch + 1 < 4) {
            stage(s ^ 1, (ch + 1) << 5);
            asm volatile("cp.async.wait_group 1;");
        } else {
            asm volatile("cp.async.wait_group 0;");
        }
        __syncthreads();

        const float* Abuf = smemf + s * CLS_ABUF;
        const int kcg = ch << 5;

        #pragma unroll
        for (int kb = 0; kb < 32; kb += 8) {
            uint32_t a[2][4];
            #pragma unroll
            for (int mi = 0; mi < 2; mi++) {
                int R = wid * 32 + mi * 16;
                a[mi][0] = __float_as_uint(Abuf[(R + gid) * 36 + kb + tig]);
                a[mi][1] = __float_as_uint(Abuf[(R + gid + 8) * 36 + kb + tig]);
                a[mi][2] = __float_as_uint(Abuf[(R + gid) * 36 + kb + tig + 4]);
                a[mi][3] = __float_as_uint(Abuf[(R + gid + 8) * 36 + kb + tig + 4]);
            }
            #pragma unroll
            for (int ni = 0; ni < 8; ni++) {
                uint32_t b0 = __float_as_uint(Bs[(ni * 8 + gid) * 132 + kcg + kb + tig]);
                uint32_t b1 = __float_as_uint(Bs[(ni * 8 + gid) * 132 + kcg + kb + tig + 4]);
                #pragma unroll
                for (int mi = 0; mi < 2; mi++) {
                    asm volatile(
                        "mma.sync.aligned.m16n8k8.row.col.f32.tf32.tf32.f32 "
                        "{%0,%1,%2,%3}, {%4,%5,%6,%7}, {%8,%9}, {%0,%1,%2,%3};"
                        : "+f"(acc[mi][ni][0]), "+f"(acc[mi][ni][1]),
                          "+f"(acc[mi][ni][2]), "+f"(acc[mi][ni][3])
                        : "r"(a[mi][0]), "r"(a[mi][1]), "r"(a[mi][2]), "r"(a[mi][3]),
                          "r"(b0), "r"(b1));
                }
            }
        }
        __syncthreads();
    }

    // bias for this lane's columns (ni < 5 covers cols 0..39)
    float bv[5][2];
    #pragma unroll
    for (int ni = 0; ni < 5; ni++) {
        int c = ni * 8 + tig * 2;
        bv[ni][0] = bias[c];
        bv[ni][1] = bias[c + 1];
    }

    // per-row log_softmax: a row's 40 logits live on the 4 lanes of one quad
    #pragma unroll
    for (int mi = 0; mi < 2; mi++) {
        #pragma unroll
        for (int h = 0; h < 2; h++) {
            int row = tile0 + wid * 32 + mi * 16 + h * 8 + gid;
            float l[5][2];
            float mx = -INFINITY;
            #pragma unroll
            for (int ni = 0; ni < 5; ni++) {
                l[ni][0] = acc[mi][ni][2 * h] + bv[ni][0];
                l[ni][1] = acc[mi][ni][2 * h + 1] + bv[ni][1];
                mx = fmaxf(mx, fmaxf(l[ni][0], l[ni][1]));
            }
            mx = fmaxf(mx, __shfl_xor_sync(0xffffffffu, mx, 1));
            mx = fmaxf(mx, __shfl_xor_sync(0xffffffffu, mx, 2));
            float se = 0.f;
            #pragma unroll
            for (int ni = 0; ni < 5; ni++)
                se += __expf(l[ni][0] - mx) + __expf(l[ni][1] - mx);
            se += __shfl_xor_sync(0xffffffffu, se, 1);
            se += __shfl_xor_sync(0xffffffffu, se, 2);
            float ls = mx + __logf(se);
            if (row < Nrows) {
                float* o = out + (size_t)row * NCLASS;
                #pragma unroll
                for (int ni = 0; ni < 5; ni++) {
                    int c = ni * 8 + tig * 2;
                    o[c]     = l[ni][0] - ls;
                    o[c + 1] = l[ni][1] - ls;
                }
            }
        }
    }
}

// ---------------- CSR SpMM (fp16 gather) fused with SAGE epilogue -----------
__global__ void spmm_relu_kernel(const __half* __restrict__ P,
                                 const float* __restrict__ S,
                                 float* __restrict__ H)
{
    int warp = (blockIdx.x * blockDim.x + threadIdx.x) >> 5;
    int lane = threadIdx.x & 31;
    if (warp >= NNODES) return;
    int r = warp;
    int start = g_rowptr[r], end = g_rowptr[r + 1];

    float4 acc = make_float4(0.f, 0.f, 0.f, 0.f);
    for (int base = start; base < end; base += 32) {
        int idx = base + lane;
        int c = (idx < end) ? g_colidx[idx] : 0;
        int cnt = min(32, end - base);
        #pragma unroll 4
        for (int j = 0; j < cnt; j++) {
            int cj = __shfl_sync(0xffffffffu, c, j);
            uint2 raw = *reinterpret_cast<const uint2*>(P + (size_t)cj * 128 + lane * 4);
            float2 f0 = __half22float2(*reinterpret_cast<__half2*>(&raw.x));
            float2 f1 = __half22float2(*reinterpret_cast<__half2*>(&raw.y));
            acc.x += f0.x; acc.y += f0.y; acc.z += f1.x; acc.w += f1.y;
        }
    }
    float inv = g_invdeg[r];
    float4 s = *reinterpret_cast<const float4*>(S + (size_t)r * 128 + lane * 4);
    float4 h;
    h.x = fmaxf(fmaf(acc.x, inv, s.x), 0.f);
    h.y = fmaxf(fmaf(acc.y, inv, s.y), 0.f);
    h.z = fmaxf(fmaf(acc.z, inv, s.z), 0.f);
    h.w = fmaxf(fmaf(acc.w, inv, s.w), 0.f);
    *reinterpret_cast<float4*>(H + (size_t)r * 128 + lane * 4) = h;
}

// ---------------- launch ----------------
extern "C" void kernel_launch(void* const* d_in, const int* in_sizes, int n_in,
                              void* d_out, int out_size) {
    const float* x     = (const float*)d_in[0];   // [N,256]
    const float* W1    = (const float*)d_in[1];   // [128,512]
    const float* W2    = (const float*)d_in[2];   // [128,256]
    const float* mlpW  = (const float*)d_in[3];   // [40,128]
    const float* mlpb  = (const float*)d_in[4];   // [40]
    const int*   erow  = (const int*)d_in[5];
    const int*   ecol  = (const int*)d_in[6];
    int E = in_sizes[5];
    float* out = (float*)d_out;

    float *pSelf, *pH;
    __half* pPh;
    cudaGetSymbolAddress((void**)&pSelf, g_Self);
    cudaGetSymbolAddress((void**)&pPh, g_Ph);
    cudaGetSymbolAddress((void**)&pH, g_H);

    static cudaStream_t s_gemm = nullptr;
    static cudaEvent_t  ev_fork = nullptr, ev_join = nullptr;
    if (s_gemm == nullptr) {
        cudaStreamCreateWithFlags(&s_gemm, cudaStreamNonBlocking);
        cudaEventCreateWithFlags(&ev_fork, cudaEventDisableTiming);
        cudaEventCreateWithFlags(&ev_join, cudaEventDisableTiming);
        cudaFuncSetAttribute(mma_gemm_kernel,
                             cudaFuncAttributeMaxDynamicSharedMemorySize, GEMM_SMEM_BYTES);
        cudaFuncSetAttribute(cls_mma_kernel,
                             cudaFuncAttributeMaxDynamicSharedMemorySize, CLS_SMEM_BYTES);
    }

    const int nb_nodes = (NNODES + 255) / 256;
    const int nb_edges = (E + 255) / 256;
    const int nb_warps = (NNODES * 32 + 255) / 256;
    const int nb_tiles = (NNODES + 127) / 128;

    // Fork: layer-1 GEMM on side stream, CSR build on main stream (independent)
    cudaEventRecord(ev_fork, 0);
    cudaStreamWaitEvent(s_gemm, ev_fork, 0);
    mma_gemm_kernel<<<nb_tiles, 512, GEMM_SMEM_BYTES, s_gemm>>>(
        x, W1, NFEAT, 2 * NFEAT, pSelf, pPh, NNODES);
    cudaEventRecord(ev_join, s_gemm);

    k_zero_deg<<<nb_nodes, 256>>>();
    k_hist<<<nb_edges, 256>>>(erow, E);
    k_scan1<<<SCAN_NB, SCAN_B>>>();
    k_scan2<<<1, 128>>>();
    k_scan3<<<SCAN_NB, SCAN_B>>>();
    k_scatter<<<nb_edges, 256>>>(erow, ecol, E);

    // Join: SpMM needs both CSR and the layer-1 projections
    cudaStreamWaitEvent(0, ev_join, 0);
    spmm_relu_kernel<<<nb_warps, 256>>>(pPh, pSelf, pH);

    // Layer 2
    mma_gemm_kernel<<<nb_tiles, 512, GEMM_SMEM_BYTES>>>(
        pH, W2, NHID, 2 * NHID, pSelf, pPh, NNODES);
    spmm_relu_kernel<<<nb_warps, 256>>>(pPh, pSelf, pH);

    cls_mma_kernel<<<nb_tiles, 128, CLS_SMEM_BYTES>>>(pH, mlpW, mlpb, out, NNODES);
}

// round 12
// speedup vs baseline: 1.0471x; 1.0471x over previous
#include <cuda_runtime.h>
#include <cuda_fp16.h>
#include <cstdint>
#include <math.h>

#define NNODES 100000
#define NEDGES 3200000
#define NFEAT  256
#define NHID   128
#define NCLASS 40

#define SCAN_B  1024
#define SCAN_NB ((NNODES + SCAN_B - 1) / SCAN_B)   // 98

// ---------------- scratch ----------------
__device__ float  g_Self[(size_t)NNODES * NHID];
__device__ __half g_Ph[(size_t)NNODES * NHID];     // neighbor projection, fp16
__device__ float  g_H[(size_t)NNODES * NHID];
__device__ int    g_deg[NNODES];
__device__ int    g_rowptr[NNODES + 1];
__device__ int    g_cursor[NNODES];
__device__ int    g_colidx[NEDGES];
__device__ float  g_invdeg[NNODES];
__device__ int    g_blocksum[SCAN_NB];

// ---------------- CSR build ----------------
__global__ void k_zero_deg() {
    int i = blockIdx.x * blockDim.x + threadIdx.x;
    if (i < NNODES) g_deg[i] = 0;
}
__global__ void k_hist(const int* __restrict__ rows, int E) {
    int e = blockIdx.x * blockDim.x + threadIdx.x;
    if (e < E) atomicAdd(&g_deg[rows[e]], 1);
}

__global__ void k_scan1() {
    __shared__ int wsum[32];
    int tid = threadIdx.x, lane = tid & 31, wid = tid >> 5;
    int i = blockIdx.x * SCAN_B + tid;
    int v = (i < NNODES) ? g_deg[i] : 0;
    #pragma unroll
    for (int o = 16; o > 0; o >>= 1)
        v += __shfl_xor_sync(0xffffffffu, v, o);
    if (lane == 0) wsum[wid] = v;
    __syncthreads();
    if (wid == 0) {
        int y = wsum[lane];
        #pragma unroll
        for (int o = 16; o > 0; o >>= 1)
            y += __shfl_xor_sync(0xffffffffu, y, o);
        if (lane == 0) g_blocksum[blockIdx.x] = y;
    }
}

__global__ void k_scan2() {
    __shared__ int s[128];
    int tid = threadIdx.x;
    int v = (tid < SCAN_NB) ? g_blocksum[tid] : 0;
    s[tid] = v;
    __syncthreads();
    #pragma unroll
    for (int o = 1; o < 128; o <<= 1) {
        int t = (tid >= o) ? s[tid - o] : 0;
        __syncthreads();
        s[tid] += t;
        __syncthreads();
    }
    if (tid < SCAN_NB) g_blocksum[tid] = s[tid] - v;   // exclusive
    if (tid == 127) g_rowptr[NNODES] = s[127];
}

__global__ void k_scan3() {
    __shared__ int wsum[32];
    int tid = threadIdx.x, lane = tid & 31, wid = tid >> 5;
    int i = blockIdx.x * SCAN_B + tid;
    int v = (i < NNODES) ? g_deg[i] : 0;
    int x = v;
    #pragma unroll
    for (int o = 1; o < 32; o <<= 1) {
        int t = __shfl_up_sync(0xffffffffu, x, o);
        if (lane >= o) x += t;
    }
    if (lane == 31) wsum[wid] = x;
    __syncthreads();
    if (wid == 0) {
        int y = wsum[lane];
        #pragma unroll
        for (int o = 1; o < 32; o <<= 1) {
            int t = __shfl_up_sync(0xffffffffu, y, o);
            if (lane >= o) y += t;
        }
        wsum[lane] = y;
    }
    __syncthreads();
    if (i < NNODES) {
        int incl = x + (wid > 0 ? wsum[wid - 1] : 0) + g_blocksum[blockIdx.x];
        int excl = incl - v;
        g_rowptr[i] = excl;
        g_cursor[i] = excl;
        g_invdeg[i] = 1.0f / ((float)v + 1.0f);
    }
}

__global__ void k_scatter(const int* __restrict__ rows, const int* __restrict__ cols, int E) {
    int e = blockIdx.x * blockDim.x + threadIdx.x;
    if (e < E) {
        int r = rows[e];
        int p = atomicAdd(&g_cursor[r], 1);
        g_colidx[p] = cols[e];
    }
}

// ================= tf32 mma.sync GEMM, cp.async double-buffered =============
// y = blockIdx.y: 0 -> C0 fp32 (self slab of W), 1 -> C1h fp16 (neigh slab).
// Block: 256 thr / 8 warps; warp tile 32(m) x 64(n); K chunks of 32, 2 stages.
#define ABUF_F 4608            // 128*36 floats per stage
#define SMEM_FLOATS (4 * ABUF_F)
#define GEMM_SMEM_BYTES (SMEM_FLOATS * 4)

__global__ __launch_bounds__(256, 2) void mma_gemm_kernel(
    const float* __restrict__ A, const float* __restrict__ W,
    int K, int ldb,
    float* __restrict__ C0, __half* __restrict__ C1h, int Nrows)
{
    extern __shared__ float smemf[];   // [2][128][36] A, then [2][128][36] B
    const int tid = threadIdx.x;
    const int lane = tid & 31, wid = tid >> 5;
    const int warp_m = wid & 3;
    const int warp_n = wid >> 2;
    const int gid = lane >> 2, tig = lane & 3;
    const int tile0 = blockIdx.x * 128;
    const float* Bp = W + (size_t)blockIdx.y * K;
    const uint32_t smem_u32 = (uint32_t)__cvta_generic_to_shared(smemf);

    float acc[2][8][4];
    #pragma unroll
    for (int mi = 0; mi < 2; mi++)
        #pragma unroll
        for (int ni = 0; ni < 8; ni++)
            #pragma unroll
            for (int q = 0; q < 4; q++) acc[mi][ni][q] = 0.f;

    const int srow = tid >> 3;
    const int skq  = (tid & 7) << 2;
    int gr0 = tile0 + srow;

    auto stage = [&](int s, int kc) {
        #pragma unroll
        for (int it = 0; it < 4; it++) {
            int row = srow + (it << 5);
            int gr = gr0 + (it << 5);
            if (gr >= Nrows) gr = Nrows - 1;
            const float* ga = A + (size_t)gr * K + kc + skq;
            uint32_t da = smem_u32 + (uint32_t)((s * ABUF_F + row * 36 + skq) << 2);
            asm volatile("cp.async.ca.shared.global [%0], [%1], 16;" :: "r"(da), "l"(ga));
            const float* gb = Bp + (size_t)row * ldb + kc + skq;
            uint32_t db = smem_u32 + (uint32_t)(((2 * ABUF_F) + s * ABUF_F + row * 36 + skq) << 2);
            asm volatile("cp.async.ca.shared.global [%0], [%1], 16;" :: "r"(db), "l"(gb));
        }
        asm volatile("cp.async.commit_group;");
    };

    const int nch = K >> 5;
    stage(0, 0);

    for (int ch = 0; ch < nch; ch++) {
        const int s = ch & 1;
        if (ch + 1 < nch) {
            stage(s ^ 1, (ch + 1) << 5);
            asm volatile("cp.async.wait_group 1;");
        } else {
            asm volatile("cp.async.wait_group 0;");
        }
        __syncthreads();

        const float* Abuf = smemf + s * ABUF_F;
        const float* Bbuf = smemf + 2 * ABUF_F + s * ABUF_F;

        #pragma unroll
        for (int kb = 0; kb < 32; kb += 8) {
            uint32_t a[2][4];
            #pragma unroll
            for (int mi = 0; mi < 2; mi++) {
                int R = warp_m * 32 + mi * 16;
                a[mi][0] = __float_as_uint(Abuf[(R + gid) * 36 + kb + tig]);
                a[mi][1] = __float_as_uint(Abuf[(R + gid + 8) * 36 + kb + tig]);
                a[mi][2] = __float_as_uint(Abuf[(R + gid) * 36 + kb + tig + 4]);
                a[mi][3] = __float_as_uint(Abuf[(R + gid + 8) * 36 + kb + tig + 4]);
            }
            #pragma unroll
            for (int ni = 0; ni < 8; ni++) {
                int n0 = warp_n * 64 + ni * 8;
                uint32_t b0 = __float_as_uint(Bbuf[(n0 + gid) * 36 + kb + tig]);
                uint32_t b1 = __float_as_uint(Bbuf[(n0 + gid) * 36 + kb + tig + 4]);
                #pragma unroll
                for (int mi = 0; mi < 2; mi++) {
                    asm volatile(
                        "mma.sync.aligned.m16n8k8.row.col.f32.tf32.tf32.f32 "
                        "{%0,%1,%2,%3}, {%4,%5,%6,%7}, {%8,%9}, {%0,%1,%2,%3};"
                        : "+f"(acc[mi][ni][0]), "+f"(acc[mi][ni][1]),
                          "+f"(acc[mi][ni][2]), "+f"(acc[mi][ni][3])
                        : "r"(a[mi][0]), "r"(a[mi][1]), "r"(a[mi][2]), "r"(a[mi][3]),
                          "r"(b0), "r"(b1));
                }
            }
        }
        __syncthreads();
    }

    const bool half_out = (blockIdx.y != 0);
    #pragma unroll
    for (int mi = 0; mi < 2; mi++) {
        int r0 = tile0 + warp_m * 32 + mi * 16 + gid;
        #pragma unroll
        for (int ni = 0; ni < 8; ni++) {
            int c = warp_n * 64 + ni * 8 + tig * 2;
            if (half_out) {
                if (r0 < Nrows)
                    *reinterpret_cast<__half2*>(C1h + (size_t)r0 * 128 + c) =
                        __floats2half2_rn(acc[mi][ni][0], acc[mi][ni][1]);
                if (r0 + 8 < Nrows)
                    *reinterpret_cast<__half2*>(C1h + (size_t)(r0 + 8) * 128 + c) =
                        __floats2half2_rn(acc[mi][ni][2], acc[mi][ni][3]);
            } else {
                if (r0 < Nrows)
                    *reinterpret_cast<float2*>(C0 + (size_t)r0 * 128 + c) =
                        make_float2(acc[mi][ni][0], acc[mi][ni][1]);
                if (r0 + 8 < Nrows)
                    *reinterpret_cast<float2*>(C0 + (size_t)(r0 + 8) * 128 + c) =
                        make_float2(acc[mi][ni][2], acc[mi][ni][3]);
            }
        }
    }
}

// ========== Classifier: tf32 mma GEMM + fused bias + log_softmax ============
// Tile 128 rows x 64 cols (W zero-padded 40->64). 4 warps; each warp owns ALL
// 64 cols of its 32 rows -> row softmax reduces within a quad (shfl xor 1,2).
#define CLS_ABUF 4608                               // 128*36 per stage
#define CLS_BOFF (2 * CLS_ABUF)
#define CLS_BF   (64 * 132)
#define CLS_SMEM_BYTES ((2 * CLS_ABUF + CLS_BF) * 4)   // 70,656 B

__global__ __launch_bounds__(128, 2) void cls_mma_kernel(
    const float* __restrict__ A, const float* __restrict__ W,
    const float* __restrict__ bias, float* __restrict__ out, int Nrows)
{
    extern __shared__ float smemf[];
    float* Bs = smemf + CLS_BOFF;                  // [64][132]
    const int tid = threadIdx.x;
    const int lane = tid & 31, wid = tid >> 5;     // wid = warp_m
    const int gid = lane >> 2, tig = lane & 3;
    const int tile0 = blockIdx.x * 128;
    const uint32_t smem_u32 = (uint32_t)__cvta_generic_to_shared(smemf);

    // Load W (40x128) into padded Bs (64x128, rows 40..63 = 0)
    for (int idx = tid; idx < 64 * 128; idx += 128) {
        int r = idx >> 7, k = idx & 127;
        Bs[r * 132 + k] = (r < NCLASS) ? W[r * 128 + k] : 0.f;
    }

    float acc[2][8][4];
    #pragma unroll
    for (int mi = 0; mi < 2; mi++)
        #pragma unroll
        for (int ni = 0; ni < 8; ni++)
            #pragma unroll
            for (int q = 0; q < 4; q++) acc[mi][ni][q] = 0.f;

    auto stage = [&](int s, int kc) {
        #pragma unroll
        for (int it = 0; it < 8; it++) {
            int idx = tid + (it << 7);
            int row = idx >> 3, kq = (idx & 7) << 2;
            int gr = tile0 + row;
            if (gr >= Nrows) gr = Nrows - 1;
            const float* ga = A + (size_t)gr * NHID + kc + kq;
            uint32_t da = smem_u32 + (uint32_t)((s * CLS_ABUF + row * 36 + kq) << 2);
            asm volatile("cp.async.ca.shared.global [%0], [%1], 16;" :: "r"(da), "l"(ga));
        }
        asm volatile("cp.async.commit_group;");
    };

    stage(0, 0);

    #pragma unroll
    for (int ch = 0; ch < 4; ch++) {               // K = 128
        const int s = ch & 1;
        if (ch + 1 < 4) {
            stage(s ^ 1, (ch + 1) << 5);
            asm volatile("cp.async.wait_group 1;");
        } else {
            asm volatile("cp.async.wait_group 0;");
        }
        __syncthreads();

        const float* Abuf = smemf + s * CLS_ABUF;
        const int kcg = ch << 5;

        #pragma unroll
        for (int kb = 0; kb < 32; kb += 8) {
            uint32_t a[2][4];
            #pragma unroll
            for (int mi = 0; mi < 2; mi++) {
                int R = wid * 32 + mi * 16;
                a[mi][0] = __float_as_uint(Abuf[(R + gid) * 36 + kb + tig]);
                a[mi][1] = __float_as_uint(Abuf[(R + gid + 8) * 36 + kb + tig]);
                a[mi][2] = __float_as_uint(Abuf[(R + gid) * 36 + kb + tig + 4]);
                a[mi][3] = __float_as_uint(Abuf[(R + gid + 8) * 36 + kb + tig + 4]);
            }
            #pragma unroll
            for (int ni = 0; ni < 8; ni++) {
                uint32_t b0 = __float_as_uint(Bs[(ni * 8 + gid) * 132 + kcg + kb + tig]);
                uint32_t b1 = __float_as_uint(Bs[(ni * 8 + gid) * 132 + kcg + kb + tig + 4]);
                #pragma unroll
                for (int mi = 0; mi < 2; mi++) {
                    asm volatile(
                        "mma.sync.aligned.m16n8k8.row.col.f32.tf32.tf32.f32 "
                        "{%0,%1,%2,%3}, {%4,%5,%6,%7}, {%8,%9}, {%0,%1,%2,%3};"
                        : "+f"(acc[mi][ni][0]), "+f"(acc[mi][ni][1]),
                          "+f"(acc[mi][ni][2]), "+f"(acc[mi][ni][3])
                        : "r"(a[mi][0]), "r"(a[mi][1]), "r"(a[mi][2]), "r"(a[mi][3]),
                          "r"(b0), "r"(b1));
                }
            }
        }
        __syncthreads();
    }

    // bias for this lane's columns (ni < 5 covers cols 0..39)
    float bv[5][2];
    #pragma unroll
    for (int ni = 0; ni < 5; ni++) {
        int c = ni * 8 + tig * 2;
        bv[ni][0] = bias[c];
        bv[ni][1] = bias[c + 1];
    }

    // per-row log_softmax: a row's 40 logits live on the 4 lanes of one quad
    #pragma unroll
    for (int mi = 0; mi < 2; mi++) {
        #pragma unroll
        for (int h = 0; h < 2; h++) {
            int row = tile0 + wid * 32 + mi * 16 + h * 8 + gid;
            float l[5][2];
            float mx = -INFINITY;
            #pragma unroll
            for (int ni = 0; ni < 5; ni++) {
                l[ni][0] = acc[mi][ni][2 * h] + bv[ni][0];
                l[ni][1] = acc[mi][ni][2 * h + 1] + bv[ni][1];
                mx = fmaxf(mx, fmaxf(l[ni][0], l[ni][1]));
            }
            mx = fmaxf(mx, __shfl_xor_sync(0xffffffffu, mx, 1));
            mx = fmaxf(mx, __shfl_xor_sync(0xffffffffu, mx, 2));
            float se = 0.f;
            #pragma unroll
            for (int ni = 0; ni < 5; ni++)
                se += __expf(l[ni][0] - mx) + __expf(l[ni][1] - mx);
            se += __shfl_xor_sync(0xffffffffu, se, 1);
            se += __shfl_xor_sync(0xffffffffu, se, 2);
            float ls = mx + __logf(se);
            if (row < Nrows) {
                float* o = out + (size_t)row * NCLASS;
                #pragma unroll
                for (int ni = 0; ni < 5; ni++) {
                    int c = ni * 8 + tig * 2;
                    o[c]     = l[ni][0] - ls;
                    o[c + 1] = l[ni][1] - ls;
                }
            }
        }
    }
}

// ---------------- CSR SpMM (fp16 gather) fused with SAGE epilogue -----------
__global__ void spmm_relu_kernel(const __half* __restrict__ P,
                                 const float* __restrict__ S,
                                 float* __restrict__ H)
{
    int warp = (blockIdx.x * blockDim.x + threadIdx.x) >> 5;
    int lane = threadIdx.x & 31;
    if (warp >= NNODES) return;
    int r = warp;
    int start = g_rowptr[r], end = g_rowptr[r + 1];

    float4 acc = make_float4(0.f, 0.f, 0.f, 0.f);
    for (int base = start; base < end; base += 32) {
        int idx = base + lane;
        int c = (idx < end) ? g_colidx[idx] : 0;
        int cnt = min(32, end - base);
        #pragma unroll 4
        for (int j = 0; j < cnt; j++) {
            int cj = __shfl_sync(0xffffffffu, c, j);
            uint2 raw = *reinterpret_cast<const uint2*>(P + (size_t)cj * 128 + lane * 4);
            float2 f0 = __half22float2(*reinterpret_cast<__half2*>(&raw.x));
            float2 f1 = __half22float2(*reinterpret_cast<__half2*>(&raw.y));
            acc.x += f0.x; acc.y += f0.y; acc.z += f1.x; acc.w += f1.y;
        }
    }
    float inv = g_invdeg[r];
    float4 s = *reinterpret_cast<const float4*>(S + (size_t)r * 128 + lane * 4);
    float4 h;
    h.x = fmaxf(fmaf(acc.x, inv, s.x), 0.f);
    h.y = fmaxf(fmaf(acc.y, inv, s.y), 0.f);
    h.z = fmaxf(fmaf(acc.z, inv, s.z), 0.f);
    h.w = fmaxf(fmaf(acc.w, inv, s.w), 0.f);
    *reinterpret_cast<float4*>(H + (size_t)r * 128 + lane * 4) = h;
}

// ---------------- launch ----------------
extern "C" void kernel_launch(void* const* d_in, const int* in_sizes, int n_in,
                              void* d_out, int out_size) {
    const float* x     = (const float*)d_in[0];   // [N,256]
    const float* W1    = (const float*)d_in[1];   // [128,512]
    const float* W2    = (const float*)d_in[2];   // [128,256]
    const float* mlpW  = (const float*)d_in[3];   // [40,128]
    const float* mlpb  = (const float*)d_in[4];   // [40]
    const int*   erow  = (const int*)d_in[5];
    const int*   ecol  = (const int*)d_in[6];
    int E = in_sizes[5];
    float* out = (float*)d_out;

    float *pSelf, *pH;
    __half* pPh;
    cudaGetSymbolAddress((void**)&pSelf, g_Self);
    cudaGetSymbolAddress((void**)&pPh, g_Ph);
    cudaGetSymbolAddress((void**)&pH, g_H);

    static cudaStream_t s_gemm = nullptr;
    static cudaEvent_t  ev_fork = nullptr, ev_join = nullptr;
    if (s_gemm == nullptr) {
        cudaStreamCreateWithFlags(&s_gemm, cudaStreamNonBlocking);
        cudaEventCreateWithFlags(&ev_fork, cudaEventDisableTiming);
        cudaEventCreateWithFlags(&ev_join, cudaEventDisableTiming);
        cudaFuncSetAttribute(mma_gemm_kernel,
                             cudaFuncAttributeMaxDynamicSharedMemorySize, GEMM_SMEM_BYTES);
        cudaFuncSetAttribute(cls_mma_kernel,
                             cudaFuncAttributeMaxDynamicSharedMemorySize, CLS_SMEM_BYTES);
    }

    const int nb_nodes = (NNODES + 255) / 256;
    const int nb_edges = (E + 255) / 256;
    const int nb_warps = (NNODES * 32 + 255) / 256;
    const int nb_tiles = (NNODES + 127) / 128;
    dim3 g1(nb_tiles, 2);

    // Fork: layer-1 GEMM on side stream, CSR build on main stream (independent)
    cudaEventRecord(ev_fork, 0);
    cudaStreamWaitEvent(s_gemm, ev_fork, 0);
    mma_gemm_kernel<<<g1, 256, GEMM_SMEM_BYTES, s_gemm>>>(x, W1, NFEAT, 2 * NFEAT,
                                                          pSelf, pPh, NNODES);
    cudaEventRecord(ev_join, s_gemm);

    k_zero_deg<<<nb_nodes, 256>>>();
    k_hist<<<nb_edges, 256>>>(erow, E);
    k_scan1<<<SCAN_NB, SCAN_B>>>();
    k_scan2<<<1, 128>>>();
    k_scan3<<<SCAN_NB, SCAN_B>>>();
    k_scatter<<<nb_edges, 256>>>(erow, ecol, E);

    // Join: SpMM needs both CSR and the layer-1 projections
    cudaStreamWaitEvent(0, ev_join, 0);
    spmm_relu_kernel<<<nb_warps, 256>>>(pPh, pSelf, pH);

    // Layer 2
    mma_gemm_kernel<<<g1, 256, GEMM_SMEM_BYTES>>>(pH, W2, NHID, 2 * NHID,
                                                  pSelf, pPh, NNODES);
    spmm_relu_kernel<<<nb_warps, 256>>>(pPh, pSelf, pH);

    cls_mma_kernel<<<nb_tiles, 128, CLS_SMEM_BYTES>>>(pH, mlpW, mlpb, out, NNODES);
}